// round 17
// baseline (speedup 1.0000x reference)
#include <cuda_runtime.h>
#include <cuda_fp16.h>
#include <math.h>
#include <stdint.h>

#define BDIM 4
#define NTOK 4096
#define CDIM 384
#define NHEAD 8
#define HDIM 48
#define NKTOK 1024
#define WIMG 64
#define WKIMG 32
#define LOG2E 1.4426950408889634f
#define QS_LOG2E (0.14433756729740643f * 1.4426950408889634f)  // 48^-.5 * log2(e)

// -------- scratch --------
__device__ __half g_xh [BDIM * NTOK  * CDIM];
__device__ __half g_xkh[BDIM * NKTOK * CDIM];
__device__ __half g_aoh[BDIM * NTOK  * CDIM];
__device__ __half g_qh [BDIM * NTOK  * CDIM];
__device__ __half g_kh [BDIM * NKTOK * CDIM];
__device__ __half g_vt [BDIM * NHEAD * HDIM * NKTOK];
__device__ __half g_wh [4 * CDIM * CDIM];

__device__ __forceinline__ void mma_f16(float* d, uint32_t a0, uint32_t a1,
                                        uint32_t a2, uint32_t a3,
                                        uint32_t b0, uint32_t b1) {
    asm volatile(
        "mma.sync.aligned.m16n8k16.row.col.f32.f16.f16.f32 "
        "{%0,%1,%2,%3}, {%4,%5,%6,%7}, {%8,%9}, {%0,%1,%2,%3};"
        : "+f"(d[0]), "+f"(d[1]), "+f"(d[2]), "+f"(d[3])
        : "r"(a0), "r"(a1), "r"(a2), "r"(a3), "r"(b0), "r"(b1));
}
__device__ __forceinline__ void ldmx4(uint32_t& r0, uint32_t& r1,
                                      uint32_t& r2, uint32_t& r3, uint32_t addr) {
    asm volatile("ldmatrix.sync.aligned.m8n8.x4.shared.b16 {%0,%1,%2,%3}, [%4];"
                 : "=r"(r0), "=r"(r1), "=r"(r2), "=r"(r3) : "r"(addr));
}
__device__ __forceinline__ void cpasync16(uint32_t dst, const void* src) {
    asm volatile("cp.async.ca.shared.global [%0], [%1], 16;" :: "r"(dst), "l"(src));
}
__device__ __forceinline__ void cpcommit() {
    asm volatile("cp.async.commit_group;" ::: "memory");
}
__device__ __forceinline__ void cpwait0() {
    asm volatile("cp.async.wait_group 0;" ::: "memory");
}
__device__ __forceinline__ uint32_t pack_h2(float lo, float hi) {
    __half2 h = __floats2half2_rn(lo, hi);
    return *(uint32_t*)&h;
}
__device__ __forceinline__ uint32_t ex2_h2(uint32_t x) {
    uint32_t r;
    asm("ex2.approx.f16x2 %0, %1;" : "=r"(r) : "r"(x));
    return r;
}

// ============================================================
// fp32 -> fp16 converters
// ============================================================
__global__ void f2h_kernel(const float* __restrict__ s, __half* __restrict__ d) {
    int i = (blockIdx.x * blockDim.x + threadIdx.x) * 4;
    float4 v = *(const float4*)(s + i);
    *(uint32_t*)(d + i)     = pack_h2(v.x, v.y);
    *(uint32_t*)(d + i + 2) = pack_h2(v.z, v.w);
}
__global__ void f2h_w_kernel(const float* __restrict__ w0, const float* __restrict__ w1,
                             const float* __restrict__ w2, const float* __restrict__ w3) {
    int seg = blockIdx.y;
    const float* s = seg == 0 ? w0 : seg == 1 ? w1 : seg == 2 ? w2 : w3;
    __half* d = g_wh + (size_t)seg * CDIM * CDIM;
    int i = (blockIdx.x * blockDim.x + threadIdx.x) * 4;
    float4 v = *(const float4*)(s + i);
    *(uint32_t*)(d + i)     = pack_h2(v.x, v.y);
    *(uint32_t*)(d + i + 2) = pack_h2(v.z, v.w);
}

// ============================================================
// depthwise 2x2 stride-2 conv + BN (eval) -> fp16
// ============================================================
__global__ void conv_bn_kernel(const float* __restrict__ x,
                               const float* __restrict__ srw,
                               const float* __restrict__ srb,
                               const float* __restrict__ gam,
                               const float* __restrict__ bet,
                               const float* __restrict__ mu,
                               const float* __restrict__ var) {
    int c  = threadIdx.x;
    int bm = blockIdx.x;
    int b  = bm / NKTOK;
    int m  = bm % NKTOK;
    int i  = m / WKIMG;
    int j  = m % WKIMG;
    int n  = (2 * i) * WIMG + 2 * j;
    size_t base = ((size_t)b * NTOK + n) * CDIM + c;

    float w0 = srw[c * 4 + 0], w1 = srw[c * 4 + 1];
    float w2 = srw[c * 4 + 2], w3 = srw[c * 4 + 3];
    float y = x[base] * w0 + x[base + CDIM] * w1
            + x[base + (size_t)WIMG * CDIM] * w2
            + x[base + (size_t)(WIMG + 1) * CDIM] * w3;
    y += srb[c];
    float inv = rsqrtf(var[c] + 1e-5f) * gam[c];
    y = (y - mu[c]) * inv + bet[c];
    g_xkh[(size_t)bm * CDIM + c] = __float2half_rn(y);
}

// ============================================================
// fp16 GEMM: 64x128 block, 128 thr (4 warps, 2x2 grid of
// 32x64 warp tiles), cp.async double-buffered + ldmatrix.
// MODE 0: fp32 + bias   MODE 1: fp16 * QS_LOG2E   MODE 2: fp16
// MODE 3: A=Wv, W=xk -> Out[chan][token] stored as [b,h,d,m]
// ============================================================
#define HP 20    // uint32 (half2) pitch per row
template<int MODE>
__global__ __launch_bounds__(128, 3)
void gemm_f16(const __half* __restrict__ A,
              const __half* __restrict__ W,
              const float* __restrict__ bias,
              float* __restrict__ outf,
              __half* __restrict__ outh) {
    __shared__ uint32_t sA[2][64 * HP];
    __shared__ uint32_t sB[2][128 * HP];

    int row0 = blockIdx.y * 64;
    int col0 = blockIdx.x * 128;
    int t = threadIdx.x;
    int w = t >> 5, l = t & 31;
    int quad = l >> 2, qt = l & 3;
    int wm = w & 1, wn = w >> 1;           // 2x2 warp grid, tile 32x64
    int lm_row = l & 15, lm_hi = (l >> 4) * 4;

    uint32_t sAb[2] = {(uint32_t)__cvta_generic_to_shared(&sA[0][0]),
                       (uint32_t)__cvta_generic_to_shared(&sA[1][0])};
    uint32_t sBb[2] = {(uint32_t)__cvta_generic_to_shared(&sB[0][0]),
                       (uint32_t)__cvta_generic_to_shared(&sB[1][0])};

    float acc[2][8][4];
#pragma unroll
    for (int mi = 0; mi < 2; mi++)
#pragma unroll
        for (int i = 0; i < 8; i++)
#pragma unroll
            for (int j = 0; j < 4; j++) acc[mi][i][j] = 0.f;

    // per k32-tile: A 64 rows x 4 chunks, B 128 rows x 4 chunks
    auto pf = [&](int k0, int s) {
#pragma unroll
        for (int i = 0; i < 6; i++) {
            int idx = t + i * 128;             // 0..767
            if (idx < 256) {
                int r = idx >> 2, c = idx & 3;
                cpasync16(sAb[s] + (uint32_t)(r * HP + c * 4) * 4,
                          A + (size_t)(row0 + r) * 384 + k0 + c * 8);
            } else {
                int id2 = idx - 256;
                int r = id2 >> 2, c = id2 & 3;
                cpasync16(sBb[s] + (uint32_t)(r * HP + c * 4) * 4,
                          W + (size_t)(col0 + r) * 384 + k0 + c * 8);
            }
        }
    };

    pf(0, 0);
    cpcommit();

    for (int it = 0; it < 12; it++) {
        int buf = it & 1;
        cpwait0();
        __syncthreads();
        if (it + 1 < 12) { pf((it + 1) * 32, buf ^ 1); cpcommit(); }

#pragma unroll
        for (int ks = 0; ks < 2; ks++) {
            uint32_t a[2][4];
#pragma unroll
            for (int mi = 0; mi < 2; mi++)
                ldmx4(a[mi][0], a[mi][1], a[mi][2], a[mi][3],
                      sAb[buf] + (uint32_t)((wm * 32 + mi * 16 + lm_row) * HP
                                            + ks * 8 + lm_hi) * 4);
#pragma unroll
            for (int ni2 = 0; ni2 < 4; ni2++) {
                uint32_t b0, b1, b2, b3;
                ldmx4(b0, b1, b2, b3,
                      sBb[buf] + (uint32_t)((wn * 64 + ni2 * 16 + lm_row) * HP
                                            + ks * 8 + lm_hi) * 4);
#pragma unroll
                for (int mi = 0; mi < 2; mi++) {
                    mma_f16(acc[mi][2 * ni2],     a[mi][0], a[mi][1], a[mi][2], a[mi][3], b0, b2);
                    mma_f16(acc[mi][2 * ni2 + 1], a[mi][0], a[mi][1], a[mi][2], a[mi][3], b1, b3);
                }
            }
        }
    }

#pragma unroll
    for (int mi = 0; mi < 2; mi++) {
        int r = row0 + wm * 32 + mi * 16 + quad;
#pragma unroll
        for (int nc = 0; nc < 8; nc++) {
            int c = col0 + wn * 64 + nc * 8 + qt * 2;
            float* ac = acc[mi][nc];
            if (MODE == 0) {
                float b0v = bias ? bias[c] : 0.f;
                float b1v = bias ? bias[c + 1] : 0.f;
                *(float2*)(outf + (size_t)r * 384 + c) =
                    make_float2(ac[0] + b0v, ac[1] + b1v);
                *(float2*)(outf + (size_t)(r + 8) * 384 + c) =
                    make_float2(ac[2] + b0v, ac[3] + b1v);
            } else if (MODE == 1) {
                *(uint32_t*)(outh + (size_t)r * 384 + c) =
                    pack_h2(ac[0] * QS_LOG2E, ac[1] * QS_LOG2E);
                *(uint32_t*)(outh + (size_t)(r + 8) * 384 + c) =
                    pack_h2(ac[2] * QS_LOG2E, ac[3] * QS_LOG2E);
            } else if (MODE == 2) {
                *(uint32_t*)(outh + (size_t)r * 384 + c) = pack_h2(ac[0], ac[1]);
                *(uint32_t*)(outh + (size_t)(r + 8) * 384 + c) = pack_h2(ac[2], ac[3]);
            } else {
                int bi = c >> 10, m = c & (NKTOK - 1);
                int hh = r / HDIM, dd = r % HDIM;
                int r8 = r + 8;
                int hh8 = r8 / HDIM, dd8 = r8 % HDIM;
                size_t o  = ((size_t)(bi * NHEAD + hh)  * HDIM + dd)  * NKTOK + m;
                size_t o8 = ((size_t)(bi * NHEAD + hh8) * HDIM + dd8) * NKTOK + m;
                *(uint32_t*)(outh + o)  = pack_h2(ac[0], ac[1]);
                *(uint32_t*)(outh + o8) = pack_h2(ac[2], ac[3]);
            }
        }
    }
}

// ============================================================
// fused attention v9: rel_pos pipelined 1 tile ahead, f16x2
// exp2, ldmatrix, fixed-max softmax, cp.async double buffer.
// block = (b, 128 q-rows, h); 256 threads (8 warps)
// ============================================================
#define KP2 28
#define VP2 36
__global__ __launch_bounds__(256, 2)
void attn_f16(const float* __restrict__ rp) {
    __shared__ uint32_t sK[2][64 * KP2];   // K [m][d] half2
    __shared__ uint32_t sV[2][48 * VP2];   // V^T [d][m] half2

    int b  = blockIdx.x;
    int n0 = blockIdx.y * 128;
    int h  = blockIdx.z;
    int t  = threadIdx.x;
    int w = t >> 5, l = t & 31;
    int quad = l >> 2, qt = l & 3;
    int rb = w * 16;
    int lm_row = l & 15, lm_hi = (l >> 4) * 4;

    uint32_t skb[2] = {(uint32_t)__cvta_generic_to_shared(&sK[0][0]),
                       (uint32_t)__cvta_generic_to_shared(&sK[1][0])};
    uint32_t svb[2] = {(uint32_t)__cvta_generic_to_shared(&sV[0][0]),
                       (uint32_t)__cvta_generic_to_shared(&sV[1][0])};

    // ---- Q fragments (half2), pre-scaled by QS_LOG2E ----
    uint32_t qa[3][4];
    {
        const __half* q0 = g_qh + ((size_t)(b * NTOK + n0 + rb + quad)) * CDIM + h * HDIM;
        const __half* q1 = q0 + (size_t)8 * CDIM;
#pragma unroll
        for (int ks = 0; ks < 3; ks++) {
            int c = ks * 16 + 2 * qt;
            qa[ks][0] = *(const uint32_t*)(q0 + c);
            qa[ks][1] = *(const uint32_t*)(q1 + c);
            qa[ks][2] = *(const uint32_t*)(q0 + c + 8);
            qa[ks][3] = *(const uint32_t*)(q1 + c + 8);
        }
    }

    float oacc[6][4];
#pragma unroll
    for (int i = 0; i < 6; i++)
#pragma unroll
        for (int j = 0; j < 4; j++) oacc[i][j] = 0.f;
    float lr0 = 0.f, lr1 = 0.f;

    const float* rpb = rp + ((size_t)h * NTOK + n0 + rb + quad) * NKTOK;

    auto prefetch = [&](int mt, int s) {
#pragma unroll
        for (int i = 0; i < 3; i++) {
            int id = t + i * 256;
            if (id < 384) {
                int m = id / 6, c = id % 6;
                const char* src = (const char*)(g_kh +
                    ((size_t)(b * NKTOK + mt * 64 + m)) * CDIM + h * HDIM) + c * 16;
                cpasync16(skb[s] + (uint32_t)(m * KP2 + c * 4) * 4, src);
            } else {
                int id2 = id - 384;
                int d = id2 >> 3, c = id2 & 7;
                const char* src = (const char*)(g_vt +
                    ((size_t)((b * NHEAD + h) * HDIM + d)) * NKTOK + mt * 64 + c * 8);
                cpasync16(svb[s] + (uint32_t)(d * VP2 + c * 4) * 4, src);
            }
        }
    };

    // rel_pos register pipeline (1 tile ahead)
    float2 rv[16];
    auto load_rv = [&](int mt) {
        const float* rpt = rpb + mt * 64;
#pragma unroll
        for (int nc = 0; nc < 8; nc++) {
            int c = nc * 8 + qt * 2;
            rv[2 * nc]     = *(const float2*)(rpt + c);
            rv[2 * nc + 1] = *(const float2*)(rpt + (size_t)8 * NKTOK + c);
        }
    };

    prefetch(0, 0);
    cpcommit();
    load_rv(0);

    for (int mt = 0; mt < 16; mt++) {
        int buf = mt & 1;
        cpwait0();
        __syncthreads();
        if (mt + 1 < 16) { prefetch(mt + 1, buf ^ 1); cpcommit(); }

        // ---- S = Q K^T ----
        float sacc[8][4];
#pragma unroll
        for (int i = 0; i < 8; i++)
#pragma unroll
            for (int j = 0; j < 4; j++) sacc[i][j] = 0.f;
#pragma unroll
        for (int ks = 0; ks < 3; ks++) {
#pragma unroll
            for (int nc2 = 0; nc2 < 4; nc2++) {
                uint32_t b0, b1, b2, b3;
                ldmx4(b0, b1, b2, b3,
                      skb[buf] + (uint32_t)((nc2 * 16 + lm_row) * KP2 + ks * 8 + lm_hi) * 4);
                mma_f16(sacc[2 * nc2],     qa[ks][0], qa[ks][1], qa[ks][2], qa[ks][3], b0, b2);
                mma_f16(sacc[2 * nc2 + 1], qa[ks][0], qa[ks][1], qa[ks][2], qa[ks][3], b1, b3);
            }
        }

        // ---- P = 2^(S + rp*log2e): pack to half2 then f16x2 ex2 ----
        uint32_t pa[8], pb[8];
        __half2 hs0 = __floats2half2_rn(0.f, 0.f);
        __half2 hs1 = hs0;
#pragma unroll
        for (int nc = 0; nc < 8; nc++) {
            float t0 = fmaf(rv[2 * nc].x,     LOG2E, sacc[nc][0]);
            float t1 = fmaf(rv[2 * nc].y,     LOG2E, sacc[nc][1]);
            float t2 = fmaf(rv[2 * nc + 1].x, LOG2E, sacc[nc][2]);
            float t3 = fmaf(rv[2 * nc + 1].y, LOG2E, sacc[nc][3]);
            pa[nc] = ex2_h2(pack_h2(t0, t1));
            pb[nc] = ex2_h2(pack_h2(t2, t3));
            hs0 = __hadd2(hs0, *(__half2*)&pa[nc]);
            hs1 = __hadd2(hs1, *(__half2*)&pb[nc]);
        }
        lr0 += __low2float(hs0) + __high2float(hs0);
        lr1 += __low2float(hs1) + __high2float(hs1);

        // ---- rv for NEXT tile: latency covered by PV + sync + QK ----
        if (mt + 1 < 16) load_rv(mt + 1);

        // ---- PV (P C-frag layout == A-frag layout) ----
#pragma unroll
        for (int ks = 0; ks < 4; ks++) {
            uint32_t a0 = pa[2 * ks], a1 = pb[2 * ks];
            uint32_t a2 = pa[2 * ks + 1], a3 = pb[2 * ks + 1];
#pragma unroll
            for (int d2 = 0; d2 < 3; d2++) {
                uint32_t b0, b1, b2, b3;
                ldmx4(b0, b1, b2, b3,
                      svb[buf] + (uint32_t)((d2 * 16 + lm_row) * VP2 + ks * 8 + lm_hi) * 4);
                mma_f16(oacc[2 * d2],     a0, a1, a2, a3, b0, b2);
                mma_f16(oacc[2 * d2 + 1], a0, a1, a2, a3, b1, b3);
            }
        }
    }

    // ---- epilogue: row-sum reduction, normalize, fp16 store ----
    lr0 += __shfl_xor_sync(0xffffffffu, lr0, 1);
    lr0 += __shfl_xor_sync(0xffffffffu, lr0, 2);
    lr1 += __shfl_xor_sync(0xffffffffu, lr1, 1);
    lr1 += __shfl_xor_sync(0xffffffffu, lr1, 2);
    float inv0 = 1.f / lr0, inv1 = 1.f / lr1;
    size_t ob = ((size_t)(b * NTOK + n0 + rb + quad)) * CDIM + h * HDIM;
#pragma unroll
    for (int d = 0; d < 6; d++) {
        int c = d * 8 + qt * 2;
        *(uint32_t*)(g_aoh + ob + c) =
            pack_h2(oacc[d][0] * inv0, oacc[d][1] * inv0);
        *(uint32_t*)(g_aoh + ob + (size_t)8 * CDIM + c) =
            pack_h2(oacc[d][2] * inv1, oacc[d][3] * inv1);
    }
}

// ============================================================
// Launch
// ============================================================
extern "C" void kernel_launch(void* const* d_in, const int* in_sizes, int n_in,
                              void* d_out, int out_size) {
    (void)out_size;
    const float *x = nullptr, *rp = nullptr;
    const float *Wq = nullptr, *Wk = nullptr, *Wv = nullptr, *Wp = nullptr;
    const float *bp = nullptr, *srw = nullptr, *srb = nullptr;
    const float *gam = nullptr, *bet = nullptr, *mu = nullptr, *var = nullptr;
    int nW = 0, n384 = 0;
    for (int i = 0; i < n_in; i++) {
        int s = in_sizes[i];
        const float* p = (const float*)d_in[i];
        if (s == BDIM * NTOK * CDIM)            x = p;
        else if (s == NHEAD * NTOK * NKTOK)     rp = p;
        else if (s == CDIM * CDIM) {
            if (nW == 0) Wq = p; else if (nW == 1) Wk = p;
            else if (nW == 2) Wv = p; else Wp = p;
            nW++;
        }
        else if (s == CDIM * 4)                 srw = p;
        else if (s == CDIM) {
            switch (n384++) {
                case 0: bp = p; break;  case 1: srb = p; break;
                case 2: gam = p; break; case 3: bet = p; break;
                case 4: mu = p; break;  case 5: var = p; break;
            }
        }
    }

    __half *pxh, *pxkh, *paoh, *pqh, *pkh, *pvt, *pwh;
    cudaGetSymbolAddress((void**)&pxh,  g_xh);
    cudaGetSymbolAddress((void**)&pxkh, g_xkh);
    cudaGetSymbolAddress((void**)&paoh, g_aoh);
    cudaGetSymbolAddress((void**)&pqh,  g_qh);
    cudaGetSymbolAddress((void**)&pkh,  g_kh);
    cudaGetSymbolAddress((void**)&pvt,  g_vt);
    cudaGetSymbolAddress((void**)&pwh,  g_wh);

    f2h_kernel<<<(BDIM * NTOK * CDIM) / (256 * 4), 256>>>(x, pxh);
    f2h_w_kernel<<<dim3((CDIM * CDIM) / (256 * 4), 4), 256>>>(Wq, Wk, Wv, Wp);
    conv_bn_kernel<<<BDIM * NKTOK, CDIM>>>(x, srw, srb, gam, bet, mu, var);

    gemm_f16<1><<<dim3(3, (BDIM * NTOK) / 64),  128>>>(pxh,  pwh,               nullptr, nullptr, pqh);
    gemm_f16<2><<<dim3(3, (BDIM * NKTOK) / 64), 128>>>(pxkh, pwh + CDIM * CDIM, nullptr, nullptr, pkh);
    gemm_f16<3><<<dim3((BDIM * NKTOK) / 128, 6), 128>>>(pwh + 2 * CDIM * CDIM, pxkh, nullptr, nullptr, pvt);

    attn_f16<<<dim3(BDIM, NTOK / 128, NHEAD), 256>>>(rp);

    gemm_f16<0><<<dim3(3, (BDIM * NTOK) / 64), 128>>>(paoh, pwh + 3 * CDIM * CDIM, bp, (float*)d_out, nullptr);
}